// round 5
// baseline (speedup 1.0000x reference)
#include <cuda_runtime.h>
#include <math.h>

#define NWIN     2048
#define NTOK     66
#define CDIM     256
#define NHEAD    8
#define HDIM     32
#define TOKN     2
#define NTHREADS 256

// shared memory layout (floats)
#define XS_OFF   0                   // Xs[66][260]
#define OS_OFF   (XS_OFF + 66*260)   // Os[66][260]
#define QS_OFF   (OS_OFF + 66*260)   // Q[66][33]
#define KS_OFF   (QS_OFF + 66*33)
#define VS_OFF   (KS_OFF + 66*33)
#define SS_OFF   (VS_OFF + 66*33)    // S[66][67]
#define WSH_OFF  (SS_OFF + 66*67)    // Wsh[32][97]
#define TB_OFF   (WSH_OFF + 32*97)   // bias table 225*8
#define BQ_OFF   (TB_OFF + 225*8)    // qkv_b 768
#define BP_OFF   (BQ_OFF + 768)      // proj_b 256
#define SMEM_FLOATS (BP_OFF + 256)
#define SMEM_BYTES  (SMEM_FLOATS * 4)

__device__ __forceinline__ float dot32(const float* __restrict__ a,
                                       const float* __restrict__ b) {
    float s = 0.f;
#pragma unroll
    for (int c = 0; c < 32; c++) s += a[c] * b[c];
    return s;
}

__global__ void __launch_bounds__(NTHREADS, 1)
win_attn_kernel(const float* __restrict__ x,
                const float* __restrict__ qkv_w,
                const float* __restrict__ qkv_b,
                const float* __restrict__ tab,
                const float* __restrict__ proj_w,
                const float* __restrict__ proj_b,
                float* __restrict__ out)
{
    extern __shared__ float sm[];
    float* Xs  = sm + XS_OFF;
    float* Os  = sm + OS_OFF;
    float* Qs  = sm + QS_OFF;
    float* Ks  = sm + KS_OFF;
    float* Vs  = sm + VS_OFF;
    float* Ss  = sm + SS_OFF;
    float* Wsh = sm + WSH_OFF;
    float* Tb  = sm + TB_OFF;
    float* Bq  = sm + BQ_OFF;
    float* Bp  = sm + BP_OFF;

    const int tid  = threadIdx.x;
    const int tx   = tid & 15;
    const int ty   = tid >> 4;
    const int warp = tid >> 5;
    const int lane = tid & 31;
    const int win  = blockIdx.x;
    const float scale = 0.17677669529663687f;  // 1/sqrt(32)

    // ---- stage inputs ----
    const float4* xg = (const float4*)(x + (size_t)win * NTOK * CDIM);
#pragma unroll 4
    for (int idx = tid; idx < NTOK * (CDIM / 4); idx += NTHREADS) {
        int n  = idx >> 6;        // /64
        int c4 = idx & 63;
        float4 v4 = xg[n * 64 + c4];
        *(float4*)(Xs + n * 260 + c4 * 4) = v4;
    }
    for (int idx = tid; idx < 225 * 8; idx += NTHREADS) Tb[idx] = tab[idx];
    for (int idx = tid; idx < 768; idx += NTHREADS)     Bq[idx] = qkv_b[idx];
    if (tid < 256) Bp[tid] = proj_b[tid];
    __syncthreads();

    // per-thread row set for GEMM phases (5 rows; last clamped, store-guarded)
    int rows[5];
    rows[0] = ty;      rows[1] = ty + 16; rows[2] = ty + 32; rows[3] = ty + 48;
    rows[4] = (ty < 2) ? (ty + 64) : 0;

    // =========================== per-head loop ===========================
    for (int h = 0; h < NHEAD; h++) {
        // ---- GEMM1: qkv_h[66][96] = Xs[66][256] @ W_h^T ----
        float acc[5][6];
#pragma unroll
        for (int i = 0; i < 5; i++)
#pragma unroll
            for (int j = 0; j < 6; j++) acc[i][j] = 0.f;

        const float* xb0 = Xs + rows[0] * 260;
        const float* xb1 = Xs + rows[1] * 260;
        const float* xb2 = Xs + rows[2] * 260;
        const float* xb3 = Xs + rows[3] * 260;
        const float* xb4 = Xs + rows[4] * 260;

        for (int kt = 0; kt < 256; kt += 32) {
            __syncthreads();
            // stage Wsh[c][o] transposed: o in [0,96), c in [0,32)
#pragma unroll
            for (int t = 0; t < 12; t++) {
                int idx = tid + t * NTHREADS;       // 3072 elems
                int o  = idx >> 5;
                int cc = idx & 31;
                int s  = o >> 5;
                int j  = o & 31;
                Wsh[cc * 97 + o] = qkv_w[(s * 256 + h * 32 + j) * 256 + kt + cc];
            }
            __syncthreads();
#pragma unroll
            for (int cc = 0; cc < 32; cc++) {
                float xr[5], wv[6];
                xr[0] = xb0[kt + cc]; xr[1] = xb1[kt + cc]; xr[2] = xb2[kt + cc];
                xr[3] = xb3[kt + cc]; xr[4] = xb4[kt + cc];
#pragma unroll
                for (int j = 0; j < 6; j++) wv[j] = Wsh[cc * 97 + tx * 6 + j];
#pragma unroll
                for (int i = 0; i < 5; i++)
#pragma unroll
                    for (int j = 0; j < 6; j++) acc[i][j] += xr[i] * wv[j];
            }
        }

        // store q (scaled) / k / v into smem
#pragma unroll
        for (int i = 0; i < 5; i++) {
            int row = ty + 16 * i;
            if (row < NTOK) {
#pragma unroll
                for (int j = 0; j < 6; j++) {
                    int col = tx * 6 + j;
                    int s = col >> 5, d = col & 31;
                    float val = acc[i][j] + Bq[s * 256 + h * 32 + d];
                    if (s == 0)      Qs[row * 33 + d] = val * scale;
                    else if (s == 1) Ks[row * 33 + d] = val;
                    else             Vs[row * 33 + d] = val;
                }
            }
        }
        __syncthreads();

        // ---- attention: warp per row ----
        for (int r = warp; r < NTOK; r += 8) {
            const float* qrow = Qs + r * 33;
            float v0 = dot32(qrow, Ks + lane * 33);
            float v1 = dot32(qrow, Ks + (lane + 32) * 33);
            float v2 = (lane < 2) ? dot32(qrow, Ks + (lane + 64) * 33)
                                  : -INFINITY;
            // relative position bias on spatial block
            if (r >= TOKN) {
                int p  = r - TOKN;
                int ph = p >> 3, pw = p & 7;
                if (lane >= TOKN) {
                    int qp = lane - TOKN;
                    int dy = ph - (qp >> 3) + 7, dx = pw - (qp & 7) + 7;
                    v0 += Tb[(dy * 15 + dx) * 8 + h];
                }
                {
                    int qp = lane + 32 - TOKN;
                    int dy = ph - (qp >> 3) + 7, dx = pw - (qp & 7) + 7;
                    v1 += Tb[(dy * 15 + dx) * 8 + h];
                }
                if (lane < 2) {
                    int qp = lane + 64 - TOKN;
                    int dy = ph - (qp >> 3) + 7, dx = pw - (qp & 7) + 7;
                    v2 += Tb[(dy * 15 + dx) * 8 + h];
                }
            }
            // softmax across the row (66 entries spread over lanes)
            float m = fmaxf(v0, fmaxf(v1, v2));
#pragma unroll
            for (int off = 16; off > 0; off >>= 1)
                m = fmaxf(m, __shfl_xor_sync(0xffffffffu, m, off));
            float e0 = __expf(v0 - m);
            float e1 = __expf(v1 - m);
            float e2 = (lane < 2) ? __expf(v2 - m) : 0.f;
            float s = e0 + e1 + e2;
#pragma unroll
            for (int off = 16; off > 0; off >>= 1)
                s += __shfl_xor_sync(0xffffffffu, s, off);
            float inv = __frcp_rn(s);
            Ss[r * 67 + lane]      = e0 * inv;
            Ss[r * 67 + lane + 32] = e1 * inv;
            if (lane < 2) Ss[r * 67 + lane + 64] = e2 * inv;
            __syncwarp();
            // P @ V  (lane = output dim d)
            float o = 0.f;
            const float* prow = Ss + r * 67;
#pragma unroll 6
            for (int j = 0; j < NTOK; j++) o += prow[j] * Vs[j * 33 + lane];
            Os[r * 260 + h * 32 + lane] = o;
        }
        __syncthreads();
    }

    // =========================== output proj ===========================
    const float* ob0 = Os + rows[0] * 260;
    const float* ob1 = Os + rows[1] * 260;
    const float* ob2 = Os + rows[2] * 260;
    const float* ob3 = Os + rows[3] * 260;
    const float* ob4 = Os + rows[4] * 260;

    for (int nb = 0; nb < 4; nb++) {
        float acc[5][4];
#pragma unroll
        for (int i = 0; i < 5; i++)
#pragma unroll
            for (int j = 0; j < 4; j++) acc[i][j] = 0.f;

        for (int kt = 0; kt < 256; kt += 32) {
            __syncthreads();
#pragma unroll
            for (int t = 0; t < 8; t++) {
                int idx = tid + t * NTHREADS;       // 2048 elems
                int o  = idx >> 5;
                int cc = idx & 31;
                Wsh[cc * 65 + o] = proj_w[(nb * 64 + o) * 256 + kt + cc];
            }
            __syncthreads();
#pragma unroll
            for (int cc = 0; cc < 32; cc++) {
                float ar[5], wv[4];
                ar[0] = ob0[kt + cc]; ar[1] = ob1[kt + cc]; ar[2] = ob2[kt + cc];
                ar[3] = ob3[kt + cc]; ar[4] = ob4[kt + cc];
#pragma unroll
                for (int j = 0; j < 4; j++) wv[j] = Wsh[cc * 65 + tx * 4 + j];
#pragma unroll
                for (int i = 0; i < 5; i++)
#pragma unroll
                    for (int j = 0; j < 4; j++) acc[i][j] += ar[i] * wv[j];
            }
        }
        // store with bias (vectorized, coalesced)
#pragma unroll
        for (int i = 0; i < 5; i++) {
            int row = ty + 16 * i;
            if (row < NTOK) {
                int col = nb * 64 + tx * 4;
                float4 o4;
                o4.x = acc[i][0] + Bp[col + 0];
                o4.y = acc[i][1] + Bp[col + 1];
                o4.z = acc[i][2] + Bp[col + 2];
                o4.w = acc[i][3] + Bp[col + 3];
                *(float4*)(out + ((size_t)win * NTOK + row) * CDIM + col) = o4;
            }
        }
    }
}

extern "C" void kernel_launch(void* const* d_in, const int* in_sizes, int n_in,
                              void* d_out, int out_size) {
    (void)in_sizes; (void)n_in; (void)out_size;
    const float* x      = (const float*)d_in[0];
    const float* qkv_w  = (const float*)d_in[1];
    const float* qkv_b  = (const float*)d_in[2];
    const float* tab    = (const float*)d_in[3];
    const float* proj_w = (const float*)d_in[4];
    const float* proj_b = (const float*)d_in[5];
    float* out = (float*)d_out;

    cudaFuncSetAttribute(win_attn_kernel,
                         cudaFuncAttributeMaxDynamicSharedMemorySize, SMEM_BYTES);
    win_attn_kernel<<<NWIN, NTHREADS, SMEM_BYTES>>>(
        x, qkv_w, qkv_b, tab, proj_w, proj_b, out);
}